// round 1
// baseline (speedup 1.0000x reference)
#include <cuda_runtime.h>

namespace {
constexpr int kB   = 16;
constexpr int kCIN = 256;
constexpr int kL   = 2048;
constexpr int kHID = 512;
constexpr int kM   = 512;
constexpr int kLP  = 1024;
}

// Scratch (device globals — no allocation allowed)
__device__ __align__(16) float g_hp[kB * kHID * kLP];   // pooled hidden   [8192][1024]
__device__ __align__(16) float g_sc[kB * kHID * kM];    // scores/attn     [8192][512]
__device__ __align__(16) float g_hr[kB * kHID * kLP];   // retrieved       [8192][1024]

// ---------------------------------------------------------------------------
// Kernel 1: grouped 1x1 conv (G=2) + bias + ReLU + MaxPool1d(2,2)
// C[o,l] = sum_i W[o,i] * X[g*128+i, l];  hp[b,o,lp] = relu(max pair + bias)
// Tile: 64 o x 128 l, K=128 in chunks of 32. 256 thr, micro 8x4.
// ---------------------------------------------------------------------------
__global__ __launch_bounds__(256) void k1_conv_relu_pool(
    const float* __restrict__ x, const float* __restrict__ w1,
    const float* __restrict__ b1) {
  __shared__ __align__(16) float Ws[32][64];    // [k][o]
  __shared__ __align__(16) float Xs[32][128];   // [k][l]
  const int l0 = blockIdx.x * 128;
  const int o0 = blockIdx.y * 64;
  const int b  = blockIdx.z;
  const int g  = o0 >> 8;                        // group = o0/256
  const float* xb = x + ((size_t)b * kCIN + (size_t)g * 128) * kL + l0;
  const int t  = threadIdx.x;
  const int tx = t & 31;
  const int ty = t >> 5;
  float acc[8][4];
#pragma unroll
  for (int i = 0; i < 8; ++i)
#pragma unroll
    for (int j = 0; j < 4; ++j) acc[i][j] = 0.f;

  for (int k0 = 0; k0 < 128; k0 += 32) {
    {  // W tile: 64 o-rows x 32 k, transposed into smem
      const int o = t & 63, kq = t >> 6;
      const float* wp = w1 + (size_t)(o0 + o) * 128 + k0 + kq * 8;
      const float4 v0 = *(const float4*)wp;
      const float4 v1 = *(const float4*)(wp + 4);
      const int kk = kq * 8;
      Ws[kk + 0][o] = v0.x; Ws[kk + 1][o] = v0.y;
      Ws[kk + 2][o] = v0.z; Ws[kk + 3][o] = v0.w;
      Ws[kk + 4][o] = v1.x; Ws[kk + 5][o] = v1.y;
      Ws[kk + 6][o] = v1.z; Ws[kk + 7][o] = v1.w;
    }
#pragma unroll
    for (int r = 0; r < 4; ++r) {  // X tile: 32 k-rows x 128 l, direct copy
      const int idx = t + r * 256;
      const int kk = idx >> 5;
      const int l4 = (idx & 31) * 4;
      *(float4*)&Xs[kk][l4] = *(const float4*)(xb + (size_t)(k0 + kk) * kL + l4);
    }
    __syncthreads();
#pragma unroll 8
    for (int k = 0; k < 32; ++k) {
      const float4 wa = *(const float4*)&Ws[k][ty * 8];
      const float4 wb = *(const float4*)&Ws[k][ty * 8 + 4];
      const float4 xv = *(const float4*)&Xs[k][tx * 4];
      const float a[8] = {wa.x, wa.y, wa.z, wa.w, wb.x, wb.y, wb.z, wb.w};
      const float xr[4] = {xv.x, xv.y, xv.z, xv.w};
#pragma unroll
      for (int i = 0; i < 8; ++i)
#pragma unroll
        for (int j = 0; j < 4; ++j) acc[i][j] = fmaf(a[i], xr[j], acc[i][j]);
    }
    __syncthreads();
  }
  const int lp = (l0 >> 1) + tx * 2;
#pragma unroll
  for (int i = 0; i < 8; ++i) {
    const int o = o0 + ty * 8 + i;
    const float bias = b1[o];
    float2 v;
    v.x = fmaxf(fmaxf(acc[i][0], acc[i][1]) + bias, 0.f);
    v.y = fmaxf(fmaxf(acc[i][2], acc[i][3]) + bias, 0.f);
    *(float2*)&g_hp[((size_t)b * kHID + o) * kLP + lp] = v;
  }
}

// ---------------------------------------------------------------------------
// Kernel 2: scores = Hp @ P^T   (NT GEMM: [8192 x 512 x K=1024])
// Tile 64 r x 128 m, K chunks of 32. micro 8x4.
// ---------------------------------------------------------------------------
__global__ __launch_bounds__(256) void k2_scores(
    const float* __restrict__ patterns) {
  __shared__ __align__(16) float As[32][64];    // [k][r]
  __shared__ __align__(16) float Ps[32][128];   // [k][m]
  const int m0 = blockIdx.x * 128;
  const int r0 = blockIdx.y * 64;
  const int t  = threadIdx.x;
  const int tx = t & 31;
  const int ty = t >> 5;
  float acc[8][4];
#pragma unroll
  for (int i = 0; i < 8; ++i)
#pragma unroll
    for (int j = 0; j < 4; ++j) acc[i][j] = 0.f;

  for (int k0 = 0; k0 < kLP; k0 += 32) {
    {  // Hp rows -> transposed
      const int r = t & 63, kq = t >> 6;
      const float* ap = g_hp + (size_t)(r0 + r) * kLP + k0 + kq * 8;
      const float4 v0 = *(const float4*)ap;
      const float4 v1 = *(const float4*)(ap + 4);
      const int kk = kq * 8;
      As[kk + 0][r] = v0.x; As[kk + 1][r] = v0.y;
      As[kk + 2][r] = v0.z; As[kk + 3][r] = v0.w;
      As[kk + 4][r] = v1.x; As[kk + 5][r] = v1.y;
      As[kk + 6][r] = v1.z; As[kk + 7][r] = v1.w;
    }
    {  // P rows -> transposed
      const int m = t & 127, kq = t >> 7;
      const float* pp = patterns + (size_t)(m0 + m) * kLP + k0 + kq * 16;
#pragma unroll
      for (int q = 0; q < 4; ++q) {
        const float4 v = *(const float4*)(pp + q * 4);
        const int kk = kq * 16 + q * 4;
        Ps[kk + 0][m] = v.x; Ps[kk + 1][m] = v.y;
        Ps[kk + 2][m] = v.z; Ps[kk + 3][m] = v.w;
      }
    }
    __syncthreads();
#pragma unroll 8
    for (int k = 0; k < 32; ++k) {
      const float4 aa = *(const float4*)&As[k][ty * 8];
      const float4 ab = *(const float4*)&As[k][ty * 8 + 4];
      const float4 pv = *(const float4*)&Ps[k][tx * 4];
      const float a[8] = {aa.x, aa.y, aa.z, aa.w, ab.x, ab.y, ab.z, ab.w};
      const float p[4] = {pv.x, pv.y, pv.z, pv.w};
#pragma unroll
      for (int i = 0; i < 8; ++i)
#pragma unroll
        for (int j = 0; j < 4; ++j) acc[i][j] = fmaf(a[i], p[j], acc[i][j]);
    }
    __syncthreads();
  }
#pragma unroll
  for (int i = 0; i < 8; ++i) {
    const float4 v = make_float4(acc[i][0], acc[i][1], acc[i][2], acc[i][3]);
    *(float4*)&g_sc[(size_t)(r0 + ty * 8 + i) * kM + m0 + tx * 4] = v;
  }
}

// ---------------------------------------------------------------------------
// Kernel 3: softmax over m=512, one block per row
// ---------------------------------------------------------------------------
__global__ __launch_bounds__(256) void k3_softmax() {
  float* row = g_sc + (size_t)blockIdx.x * kM;
  const int t = threadIdx.x;
  const float v0 = row[t];
  const float v1 = row[t + 256];
  float m = fmaxf(v0, v1);
  __shared__ float red[8];
  __shared__ float bval;
#pragma unroll
  for (int o = 16; o; o >>= 1) m = fmaxf(m, __shfl_xor_sync(0xffffffffu, m, o));
  if ((t & 31) == 0) red[t >> 5] = m;
  __syncthreads();
  if (t == 0) {
    float mm = red[0];
#pragma unroll
    for (int i = 1; i < 8; ++i) mm = fmaxf(mm, red[i]);
    bval = mm;
  }
  __syncthreads();
  m = bval;
  const float e0 = __expf(v0 - m), e1 = __expf(v1 - m);
  float s = e0 + e1;
#pragma unroll
  for (int o = 16; o; o >>= 1) s += __shfl_xor_sync(0xffffffffu, s, o);
  __syncthreads();                     // protect red reuse
  if ((t & 31) == 0) red[t >> 5] = s;
  __syncthreads();
  if (t == 0) {
    float ss = red[0];
#pragma unroll
    for (int i = 1; i < 8; ++i) ss += red[i];
    bval = 1.f / ss;
  }
  __syncthreads();
  const float inv = bval;
  row[t] = e0 * inv;
  row[t + 256] = e1 * inv;
}

// ---------------------------------------------------------------------------
// Kernel 4: retrieval = Attn @ P   (NN GEMM: [8192 x 1024 x K=512])
// Tile 64 r x 128 l, K chunks of 32. micro 8x4.
// ---------------------------------------------------------------------------
__global__ __launch_bounds__(256) void k4_retrieve(
    const float* __restrict__ patterns) {
  __shared__ __align__(16) float As[32][64];    // [k][r]
  __shared__ __align__(16) float Ps[32][128];   // [k(m)][l]
  const int l0 = blockIdx.x * 128;
  const int r0 = blockIdx.y * 64;
  const int t  = threadIdx.x;
  const int tx = t & 31;
  const int ty = t >> 5;
  float acc[8][4];
#pragma unroll
  for (int i = 0; i < 8; ++i)
#pragma unroll
    for (int j = 0; j < 4; ++j) acc[i][j] = 0.f;

  for (int k0 = 0; k0 < kM; k0 += 32) {
    {  // attn rows -> transposed
      const int r = t & 63, kq = t >> 6;
      const float* ap = g_sc + (size_t)(r0 + r) * kM + k0 + kq * 8;
      const float4 v0 = *(const float4*)ap;
      const float4 v1 = *(const float4*)(ap + 4);
      const int kk = kq * 8;
      As[kk + 0][r] = v0.x; As[kk + 1][r] = v0.y;
      As[kk + 2][r] = v0.z; As[kk + 3][r] = v0.w;
      As[kk + 4][r] = v1.x; As[kk + 5][r] = v1.y;
      As[kk + 6][r] = v1.z; As[kk + 7][r] = v1.w;
    }
#pragma unroll
    for (int rr = 0; rr < 4; ++rr) {  // P rows: direct [m][l] copy
      const int idx = t + rr * 256;
      const int kk = idx >> 5;
      const int l4 = (idx & 31) * 4;
      *(float4*)&Ps[kk][l4] =
          *(const float4*)(patterns + (size_t)(k0 + kk) * kLP + l0 + l4);
    }
    __syncthreads();
#pragma unroll 8
    for (int k = 0; k < 32; ++k) {
      const float4 aa = *(const float4*)&As[k][ty * 8];
      const float4 ab = *(const float4*)&As[k][ty * 8 + 4];
      const float4 pv = *(const float4*)&Ps[k][tx * 4];
      const float a[8] = {aa.x, aa.y, aa.z, aa.w, ab.x, ab.y, ab.z, ab.w};
      const float p[4] = {pv.x, pv.y, pv.z, pv.w};
#pragma unroll
      for (int i = 0; i < 8; ++i)
#pragma unroll
        for (int j = 0; j < 4; ++j) acc[i][j] = fmaf(a[i], p[j], acc[i][j]);
    }
    __syncthreads();
  }
#pragma unroll
  for (int i = 0; i < 8; ++i) {
    const float4 v = make_float4(acc[i][0], acc[i][1], acc[i][2], acc[i][3]);
    *(float4*)&g_hr[(size_t)(r0 + ty * 8 + i) * kLP + l0 + tx * 4] = v;
  }
}

// ---------------------------------------------------------------------------
// Kernel 5: grouped ConvTranspose1d(k=2,s=2) + bias + ReLU + residual
// y[b, g*128+o, 2lp+k2] = sum_i hr[b, g*256+i, lp] * wT[g*256+i][o][k2]
// out = x + RZ*relu(y+bT).  Tile 64 co x 64 lp, K=256 chunks of 32.
// 256 thr, micro 4co x 4lp x 2k2.
// ---------------------------------------------------------------------------
__global__ __launch_bounds__(256) void k5_convt(
    const float* __restrict__ x, const float* __restrict__ wT,
    const float* __restrict__ bT, const float* __restrict__ rzp,
    float* __restrict__ out) {
  __shared__ __align__(16) float Hs[32][64];     // [i][lp]
  __shared__ __align__(16) float Wst[32][128];   // [i][co*2+k2]
  const int lp0 = blockIdx.x * 64;
  const int co0 = blockIdx.y * 64;
  const int bz  = blockIdx.z;
  const int b = bz >> 1, g = bz & 1;
  const int t  = threadIdx.x;
  const int tx = t & 15;
  const int ty = t >> 4;
  const float* hbase = g_hr + ((size_t)b * kHID + (size_t)g * 256) * kLP;
  const float* wbase = wT + (size_t)g * 256 * 256 + co0 * 2;
  float acc[4][4][2];
#pragma unroll
  for (int c = 0; c < 4; ++c)
#pragma unroll
    for (int j = 0; j < 4; ++j) { acc[c][j][0] = 0.f; acc[c][j][1] = 0.f; }

  for (int i0 = 0; i0 < 256; i0 += 32) {
#pragma unroll
    for (int r = 0; r < 2; ++r) {  // Hs: 32 x 64
      const int idx = t + r * 256;
      const int ii = idx >> 4;
      const int l4 = (idx & 15) * 4;
      *(float4*)&Hs[ii][l4] =
          *(const float4*)(hbase + (size_t)(i0 + ii) * kLP + lp0 + l4);
    }
#pragma unroll
    for (int r = 0; r < 4; ++r) {  // Wst: 32 x 128
      const int idx = t + r * 256;
      const int ii = idx >> 5;
      const int c4 = (idx & 31) * 4;
      *(float4*)&Wst[ii][c4] =
          *(const float4*)(wbase + (size_t)(i0 + ii) * 256 + c4);
    }
    __syncthreads();
#pragma unroll 8
    for (int i = 0; i < 32; ++i) {
      const float4 w0 = *(const float4*)&Wst[i][ty * 8];
      const float4 w1v = *(const float4*)&Wst[i][ty * 8 + 4];
      const float4 hv = *(const float4*)&Hs[i][tx * 4];
      const float wv[8] = {w0.x, w0.y, w0.z, w0.w, w1v.x, w1v.y, w1v.z, w1v.w};
      const float hh[4] = {hv.x, hv.y, hv.z, hv.w};
#pragma unroll
      for (int c = 0; c < 4; ++c)
#pragma unroll
        for (int j = 0; j < 4; ++j) {
          acc[c][j][0] = fmaf(wv[c * 2 + 0], hh[j], acc[c][j][0]);
          acc[c][j][1] = fmaf(wv[c * 2 + 1], hh[j], acc[c][j][1]);
        }
    }
    __syncthreads();
  }
  const float rz = rzp[0];
#pragma unroll
  for (int c = 0; c < 4; ++c) {
    const int cog = g * 128 + co0 + ty * 4 + c;
    const float bias = bT[cog];
    const size_t rowoff = ((size_t)b * kCIN + cog) * kL;
#pragma unroll
    for (int j = 0; j < 4; ++j) {
      const int l = 2 * (lp0 + tx * 4 + j);
      const float y0 = fmaxf(acc[c][j][0] + bias, 0.f);
      const float y1 = fmaxf(acc[c][j][1] + bias, 0.f);
      const float2 xv = *(const float2*)(x + rowoff + l);
      float2 o2;
      o2.x = xv.x + rz * y0;
      o2.y = xv.y + rz * y1;
      *(float2*)(out + rowoff + l) = o2;
    }
  }
}

// ---------------------------------------------------------------------------
extern "C" void kernel_launch(void* const* d_in, const int* in_sizes, int n_in,
                              void* d_out, int out_size) {
  (void)in_sizes; (void)n_in; (void)out_size;
  const float* x        = (const float*)d_in[0];
  const float* w1       = (const float*)d_in[1];
  const float* b1       = (const float*)d_in[2];
  const float* patterns = (const float*)d_in[3];
  const float* wT       = (const float*)d_in[4];
  const float* bT       = (const float*)d_in[5];
  const float* RZ       = (const float*)d_in[6];
  float* out            = (float*)d_out;

  k1_conv_relu_pool<<<dim3(kL / 128, kHID / 64, kB), 256>>>(x, w1, b1);
  k2_scores<<<dim3(kM / 128, (kB * kHID) / 64), 256>>>(patterns);
  k3_softmax<<<dim3(kB * kHID), 256>>>();
  k4_retrieve<<<dim3(kLP / 128, (kB * kHID) / 64), 256>>>(patterns);
  k5_convt<<<dim3(kLP / 64, 2, kB * 2), 256>>>(x, wT, bT, RZ, out);
}

// round 3
// speedup vs baseline: 2.4131x; 2.4131x over previous
#include <cuda_runtime.h>
#include <cuda_bf16.h>
#include <cstdint>

namespace {
constexpr int kB   = 16;
constexpr int kCIN = 256;
constexpr int kL   = 2048;
constexpr int kHID = 512;
constexpr int kM   = 512;
constexpr int kLP  = 1024;
constexpr int kRows = kB * kHID;  // 8192
}

// ---------------- scratch (device globals; no allocation) -------------------
__device__ __align__(16) __nv_bfloat16 g_hp[kRows * kLP];   // pooled hidden bf16
__device__ __align__(16) float         g_sc[kRows * kM];    // scores fp32
__device__ __align__(16) __nv_bfloat16 g_at[kRows * kM];    // attn bf16
__device__ __align__(16) float         g_hr[kRows * kLP];   // retrieved fp32
__device__ __align__(16) __nv_bfloat16 g_pat[kM * kLP];     // patterns bf16 [m][lp]
__device__ __align__(16) __nv_bfloat16 g_patT[kLP * kM];    // patterns^T bf16 [lp][m]

// ---------------- PTX helpers ------------------------------------------------
__device__ __forceinline__ void cp_async16(uint32_t dst, const void* src) {
  asm volatile("cp.async.cg.shared.global [%0], [%1], 16;\n" ::"r"(dst), "l"(src));
}
#define CP_COMMIT() asm volatile("cp.async.commit_group;\n" ::: "memory")
#define CP_WAIT(n) asm volatile("cp.async.wait_group %0;\n" ::"n"(n) : "memory")

__device__ __forceinline__ void ldsm_x4(uint32_t (&r)[4], uint32_t addr) {
  asm volatile(
      "ldmatrix.sync.aligned.m8n8.x4.shared.b16 {%0,%1,%2,%3}, [%4];"
      : "=r"(r[0]), "=r"(r[1]), "=r"(r[2]), "=r"(r[3])
      : "r"(addr));
}

__device__ __forceinline__ void mma_16816(float (&c)[4], const uint32_t (&a)[4],
                                          const uint32_t b0, const uint32_t b1) {
  asm volatile(
      "mma.sync.aligned.m16n8k16.row.col.f32.bf16.bf16.f32 "
      "{%0,%1,%2,%3}, {%4,%5,%6,%7}, {%8,%9}, {%0,%1,%2,%3};"
      : "+f"(c[0]), "+f"(c[1]), "+f"(c[2]), "+f"(c[3])
      : "r"(a[0]), "r"(a[1]), "r"(a[2]), "r"(a[3]), "r"(b0), "r"(b1));
}

// ---------------------------------------------------------------------------
// Kernel 1: grouped 1x1 conv (G=2) + bias + ReLU + MaxPool1d(2,2) -> bf16 g_hp
// ---------------------------------------------------------------------------
__global__ __launch_bounds__(256) void k1_conv_relu_pool(
    const float* __restrict__ x, const float* __restrict__ w1,
    const float* __restrict__ b1) {
  __shared__ __align__(16) float Ws[32][64];   // [k][o]
  __shared__ __align__(16) float Xs[32][128];  // [k][l]
  const int l0 = blockIdx.x * 128;
  const int o0 = blockIdx.y * 64;
  const int b  = blockIdx.z;
  const int g  = o0 >> 8;
  const float* xb = x + ((size_t)b * kCIN + (size_t)g * 128) * kL + l0;
  const int t  = threadIdx.x;
  const int tx = t & 31;
  const int ty = t >> 5;
  float acc[8][4];
#pragma unroll
  for (int i = 0; i < 8; ++i)
#pragma unroll
    for (int j = 0; j < 4; ++j) acc[i][j] = 0.f;

  for (int k0 = 0; k0 < 128; k0 += 32) {
    {
      const int o = t & 63, kq = t >> 6;
      const float* wp = w1 + (size_t)(o0 + o) * 128 + k0 + kq * 8;
      const float4 v0 = *(const float4*)wp;
      const float4 v1 = *(const float4*)(wp + 4);
      const int kk = kq * 8;
      Ws[kk + 0][o] = v0.x; Ws[kk + 1][o] = v0.y;
      Ws[kk + 2][o] = v0.z; Ws[kk + 3][o] = v0.w;
      Ws[kk + 4][o] = v1.x; Ws[kk + 5][o] = v1.y;
      Ws[kk + 6][o] = v1.z; Ws[kk + 7][o] = v1.w;
    }
#pragma unroll
    for (int r = 0; r < 4; ++r) {
      const int idx = t + r * 256;
      const int kk = idx >> 5;
      const int l4 = (idx & 31) * 4;
      *(float4*)&Xs[kk][l4] = *(const float4*)(xb + (size_t)(k0 + kk) * kL + l4);
    }
    __syncthreads();
#pragma unroll 8
    for (int k = 0; k < 32; ++k) {
      const float4 wa = *(const float4*)&Ws[k][ty * 8];
      const float4 wb = *(const float4*)&Ws[k][ty * 8 + 4];
      const float4 xv = *(const float4*)&Xs[k][tx * 4];
      const float a[8] = {wa.x, wa.y, wa.z, wa.w, wb.x, wb.y, wb.z, wb.w};
      const float xr[4] = {xv.x, xv.y, xv.z, xv.w};
#pragma unroll
      for (int i = 0; i < 8; ++i)
#pragma unroll
        for (int j = 0; j < 4; ++j) acc[i][j] = fmaf(a[i], xr[j], acc[i][j]);
    }
    __syncthreads();
  }
  const int lp = (l0 >> 1) + tx * 2;
#pragma unroll
  for (int i = 0; i < 8; ++i) {
    const int o = o0 + ty * 8 + i;
    const float bias = b1[o];
    __nv_bfloat162 v;
    v.x = __float2bfloat16(fmaxf(fmaxf(acc[i][0], acc[i][1]) + bias, 0.f));
    v.y = __float2bfloat16(fmaxf(fmaxf(acc[i][2], acc[i][3]) + bias, 0.f));
    *(__nv_bfloat162*)&g_hp[((size_t)b * kHID + o) * kLP + lp] = v;
  }
}

// ---------------------------------------------------------------------------
// Pattern prep: fp32 -> bf16 copy + transpose
// ---------------------------------------------------------------------------
__global__ __launch_bounds__(256) void kprep_pat(const float* __restrict__ p) {
  const int idx = blockIdx.x * 256 + threadIdx.x;
  const __nv_bfloat16 v = __float2bfloat16(p[idx]);
  const int m = idx >> 10;
  const int l = idx & 1023;
  g_pat[idx] = v;
  g_patT[(size_t)l * kM + m] = v;
}

// ---------------------------------------------------------------------------
// HMMA bf16 GEMM (mma.sync m16n8k16): C[128x128 tile] = A[r][K] * B[n][K]^T
// MODE 0: A=g_hp, B=g_pat,  C=g_sc (K=1024, ldC=512)
// MODE 1: A=g_at, B=g_patT, C=g_hr (K=512,  ldC=1024)
// BM=BN=128, BK=32; 8 warps in 2(M)x4(N); warp tile 64x32.
// smem rows padded to 40 bf16 (80B) -> conflict-free ldmatrix.
// ---------------------------------------------------------------------------
template <int K, int LDC, int MODE>
__global__ __launch_bounds__(256) void kgemm_hmma() {
  const __nv_bfloat16* A  = (MODE == 0) ? g_hp : g_at;
  const __nv_bfloat16* Bm = (MODE == 0) ? g_pat : g_patT;
  float* C                = (MODE == 0) ? g_sc : g_hr;
  constexpr int ITERS = K / 32;
  constexpr int ROWB = 80;  // padded row bytes (40 bf16)

  __shared__ __align__(16) __nv_bfloat16 sA[2][128][40];
  __shared__ __align__(16) __nv_bfloat16 sB[2][128][40];

  const int t   = threadIdx.x;
  const int w   = t >> 5;
  const int lid = t & 31;
  const int wm  = w >> 2;   // 0..1
  const int wn  = w & 3;    // 0..3
  const int n0  = blockIdx.x * 128;
  const int r0  = blockIdx.y * 128;

  const uint32_t sAb = (uint32_t)__cvta_generic_to_shared(&sA[0][0][0]);
  const uint32_t sBb = (uint32_t)__cvta_generic_to_shared(&sB[0][0][0]);
  constexpr uint32_t STAGE = 128 * ROWB;

  const char* Ab = (const char*)(A + (size_t)r0 * K);
  const char* Bb = (const char*)(Bm + (size_t)n0 * K);
  const size_t pitch = (size_t)K * 2;

  // per-thread load coords: 512 x 16B transfers per tile, 2 per thread
  const int ldrow[2] = {(t + 0) >> 2, (t + 256) >> 2};
  const int ldch[2]  = {(t + 0) & 3, (t + 256) & 3};

  auto load_tile = [&](int s, int it) {
    const size_t kbyte = (size_t)it * 64;
#pragma unroll
    for (int i = 0; i < 2; ++i) {
      const size_t go = (size_t)ldrow[i] * pitch + kbyte + ldch[i] * 16;
      const uint32_t so = (uint32_t)s * STAGE + ldrow[i] * ROWB + ldch[i] * 16;
      cp_async16(sAb + so, Ab + go);
      cp_async16(sBb + so, Bb + go);
    }
    CP_COMMIT();
  };

  float acc[4][4][4];
#pragma unroll
  for (int mt = 0; mt < 4; ++mt)
#pragma unroll
    for (int nt = 0; nt < 4; ++nt)
#pragma unroll
      for (int i = 0; i < 4; ++i) acc[mt][nt][i] = 0.f;

  load_tile(0, 0);

  // fragment smem addresses (stage 0; add s*STAGE later)
  // A: row = wm*64 + mt*16 + (lid&15); col byte = ks*32 + (lid>>4)*16
  const uint32_t aAddr0 = sAb + (wm * 64 + (lid & 15)) * ROWB + (lid >> 4) * 16;
  // B: n = wn*32 + nt2*16 + ((lid>>4)?8:0) + (lid&7); col byte = ks*32 + ((lid>>3)&1)*16
  const uint32_t bAddr0 =
      sBb + (wn * 32 + ((lid >> 4) ? 8 : 0) + (lid & 7)) * ROWB + ((lid >> 3) & 1) * 16;

#pragma unroll 1
  for (int it = 0; it < ITERS; ++it) {
    if (it + 1 < ITERS) {
      load_tile((it + 1) & 1, it + 1);
      CP_WAIT(1);
    } else {
      CP_WAIT(0);
    }
    __syncthreads();

    const uint32_t sOff = (uint32_t)(it & 1) * STAGE;
#pragma unroll
    for (int ks = 0; ks < 2; ++ks) {
      uint32_t afr[4][4];
      uint32_t bfr[4][2];
#pragma unroll
      for (int mt = 0; mt < 4; ++mt)
        ldsm_x4(afr[mt], aAddr0 + sOff + mt * 16 * ROWB + ks * 32);
#pragma unroll
      for (int nt2 = 0; nt2 < 2; ++nt2) {
        uint32_t r4[4];
        ldsm_x4(r4, bAddr0 + sOff + nt2 * 16 * ROWB + ks * 32);
        bfr[nt2 * 2 + 0][0] = r4[0]; bfr[nt2 * 2 + 0][1] = r4[1];
        bfr[nt2 * 2 + 1][0] = r4[2]; bfr[nt2 * 2 + 1][1] = r4[3];
      }
#pragma unroll
      for (int mt = 0; mt < 4; ++mt)
#pragma unroll
        for (int nt = 0; nt < 4; ++nt)
          mma_16816(acc[mt][nt], afr[mt], bfr[nt][0], bfr[nt][1]);
    }
    __syncthreads();
  }

  // epilogue: fp32 direct stores (float2 per fragment half)
  float* Crow = C + (size_t)(r0 + wm * 64) * LDC + n0 + wn * 32;
  const int rr = lid >> 2;
  const int cc = (lid & 3) * 2;
#pragma unroll
  for (int mt = 0; mt < 4; ++mt) {
#pragma unroll
    for (int nt = 0; nt < 4; ++nt) {
      float2 v0 = make_float2(acc[mt][nt][0], acc[mt][nt][1]);
      float2 v1 = make_float2(acc[mt][nt][2], acc[mt][nt][3]);
      *(float2*)&Crow[(size_t)(mt * 16 + rr) * LDC + nt * 8 + cc] = v0;
      *(float2*)&Crow[(size_t)(mt * 16 + rr + 8) * LDC + nt * 8 + cc] = v1;
    }
  }
}

// ---------------------------------------------------------------------------
// Kernel 3: softmax over m=512, writes bf16 attn
// ---------------------------------------------------------------------------
__global__ __launch_bounds__(256) void k3_softmax() {
  const float* row = g_sc + (size_t)blockIdx.x * kM;
  __nv_bfloat16* orow = g_at + (size_t)blockIdx.x * kM;
  const int t = threadIdx.x;
  const float v0 = row[t];
  const float v1 = row[t + 256];
  float m = fmaxf(v0, v1);
  __shared__ float red[8];
  __shared__ float bval;
#pragma unroll
  for (int o = 16; o; o >>= 1) m = fmaxf(m, __shfl_xor_sync(0xffffffffu, m, o));
  if ((t & 31) == 0) red[t >> 5] = m;
  __syncthreads();
  if (t == 0) {
    float mm = red[0];
#pragma unroll
    for (int i = 1; i < 8; ++i) mm = fmaxf(mm, red[i]);
    bval = mm;
  }
  __syncthreads();
  m = bval;
  const float e0 = __expf(v0 - m), e1 = __expf(v1 - m);
  float s = e0 + e1;
#pragma unroll
  for (int o = 16; o; o >>= 1) s += __shfl_xor_sync(0xffffffffu, s, o);
  __syncthreads();
  if ((t & 31) == 0) red[t >> 5] = s;
  __syncthreads();
  if (t == 0) {
    float ss = red[0];
#pragma unroll
    for (int i = 1; i < 8; ++i) ss += red[i];
    bval = 1.f / ss;
  }
  __syncthreads();
  const float inv = bval;
  orow[t] = __float2bfloat16(e0 * inv);
  orow[t + 256] = __float2bfloat16(e1 * inv);
}

// ---------------------------------------------------------------------------
// Kernel 5: grouped ConvTranspose1d(k=2,s=2) + bias + ReLU + residual
// ---------------------------------------------------------------------------
__global__ __launch_bounds__(256) void k5_convt(
    const float* __restrict__ x, const float* __restrict__ wT,
    const float* __restrict__ bT, const float* __restrict__ rzp,
    float* __restrict__ out) {
  __shared__ __align__(16) float Hs[32][64];
  __shared__ __align__(16) float Wst[32][128];
  const int lp0 = blockIdx.x * 64;
  const int co0 = blockIdx.y * 64;
  const int bz  = blockIdx.z;
  const int b = bz >> 1, g = bz & 1;
  const int t  = threadIdx.x;
  const int tx = t & 15;
  const int ty = t >> 4;
  const float* hbase = g_hr + ((size_t)b * kHID + (size_t)g * 256) * kLP;
  const float* wbase = wT + (size_t)g * 256 * 256 + co0 * 2;
  float acc[4][4][2];
#pragma unroll
  for (int c = 0; c < 4; ++c)
#pragma unroll
    for (int j = 0; j < 4; ++j) { acc[c][j][0] = 0.f; acc[c][j][1] = 0.f; }

  for (int i0 = 0; i0 < 256; i0 += 32) {
#pragma unroll
    for (int r = 0; r < 2; ++r) {
      const int idx = t + r * 256;
      const int ii = idx >> 4;
      const int l4 = (idx & 15) * 4;
      *(float4*)&Hs[ii][l4] =
          *(const float4*)(hbase + (size_t)(i0 + ii) * kLP + lp0 + l4);
    }
#pragma unroll
    for (int r = 0; r < 4; ++r) {
      const int idx = t + r * 256;
      const int ii = idx >> 5;
      const int c4 = (idx & 31) * 4;
      *(float4*)&Wst[ii][c4] =
          *(const float4*)(wbase + (size_t)(i0 + ii) * 256 + c4);
    }
    __syncthreads();
#pragma unroll 8
    for (int i = 0; i < 32; ++i) {
      const float4 w0 = *(const float4*)&Wst[i][ty * 8];
      const float4 w1v = *(const float4*)&Wst[i][ty * 8 + 4];
      const float4 hv = *(const float4*)&Hs[i][tx * 4];
      const float wv[8] = {w0.x, w0.y, w0.z, w0.w, w1v.x, w1v.y, w1v.z, w1v.w};
      const float hh[4] = {hv.x, hv.y, hv.z, hv.w};
#pragma unroll
      for (int c = 0; c < 4; ++c)
#pragma unroll
        for (int j = 0; j < 4; ++j) {
          acc[c][j][0] = fmaf(wv[c * 2 + 0], hh[j], acc[c][j][0]);
          acc[c][j][1] = fmaf(wv[c * 2 + 1], hh[j], acc[c][j][1]);
        }
    }
    __syncthreads();
  }
  const float rz = rzp[0];
#pragma unroll
  for (int c = 0; c < 4; ++c) {
    const int cog = g * 128 + co0 + ty * 4 + c;
    const float bias = bT[cog];
    const size_t rowoff = ((size_t)b * kCIN + cog) * kL;
#pragma unroll
    for (int j = 0; j < 4; ++j) {
      const int l = 2 * (lp0 + tx * 4 + j);
      const float y0 = fmaxf(acc[c][j][0] + bias, 0.f);
      const float y1 = fmaxf(acc[c][j][1] + bias, 0.f);
      const float2 xv = *(const float2*)(x + rowoff + l);
      float2 o2;
      o2.x = xv.x + rz * y0;
      o2.y = xv.y + rz * y1;
      *(float2*)(out + rowoff + l) = o2;
    }
  }
}

// ---------------------------------------------------------------------------
extern "C" void kernel_launch(void* const* d_in, const int* in_sizes, int n_in,
                              void* d_out, int out_size) {
  (void)in_sizes; (void)n_in; (void)out_size;
  const float* x        = (const float*)d_in[0];
  const float* w1       = (const float*)d_in[1];
  const float* b1       = (const float*)d_in[2];
  const float* patterns = (const float*)d_in[3];
  const float* wT       = (const float*)d_in[4];
  const float* bT       = (const float*)d_in[5];
  const float* RZ       = (const float*)d_in[6];
  float* out            = (float*)d_out;

  kprep_pat<<<(kM * kLP) / 256, 256>>>(patterns);
  k1_conv_relu_pool<<<dim3(kL / 128, kHID / 64, kB), 256>>>(x, w1, b1);
  kgemm_hmma<1024, 512, 0><<<dim3(kM / 128, kRows / 128), 256>>>();
  k3_softmax<<<kRows, 256>>>();
  kgemm_hmma<512, 1024, 1><<<dim3(kLP / 128, kRows / 128), 256>>>();
  k5_convt<<<dim3(kLP / 64, 2, kB * 2), 256>>>(x, wT, bT, RZ, out);
}

// round 4
// speedup vs baseline: 4.7100x; 1.9518x over previous
#include <cuda_runtime.h>
#include <cuda_bf16.h>
#include <cstdint>

namespace {
constexpr int kB   = 16;
constexpr int kCIN = 256;
constexpr int kL   = 2048;
constexpr int kHID = 512;
constexpr int kM   = 512;
constexpr int kLP  = 1024;
constexpr int kRows = kB * kHID;  // 8192
}

// ---------------- scratch (device globals; no allocation) -------------------
__device__ __align__(16) __nv_bfloat16 g_xb[kB * kCIN * kL];   // x bf16 (16MB)
__device__ __align__(16) __nv_bfloat16 g_w1b[kHID * 128];      // w1 bf16
__device__ __align__(16) __nv_bfloat16 g_wTt[2 * 256 * 256];   // wT^T bf16 [g][co2][i]
__device__ __align__(16) __nv_bfloat16 g_hp[kRows * kLP];      // pooled hidden bf16
__device__ __align__(16) float         g_sc[kRows * kM];       // scores fp32
__device__ __align__(16) __nv_bfloat16 g_at[kRows * kM];       // attn bf16
__device__ __align__(16) __nv_bfloat16 g_hrT[kB * kLP * kHID]; // retrieved^T bf16 [b][lp][c]
__device__ __align__(16) __nv_bfloat16 g_pat[kM * kLP];        // patterns bf16 [m][lp]
__device__ __align__(16) __nv_bfloat16 g_patT[kLP * kM];       // patterns^T bf16 [lp][m]

// ---------------- PTX helpers ------------------------------------------------
__device__ __forceinline__ void cp_async16(uint32_t dst, const void* src) {
  asm volatile("cp.async.cg.shared.global [%0], [%1], 16;\n" ::"r"(dst), "l"(src));
}
#define CP_COMMIT() asm volatile("cp.async.commit_group;\n" ::: "memory")
#define CP_WAIT(n) asm volatile("cp.async.wait_group %0;\n" ::"n"(n) : "memory")

__device__ __forceinline__ void ldsm_x4(uint32_t (&r)[4], uint32_t addr) {
  asm volatile(
      "ldmatrix.sync.aligned.m8n8.x4.shared.b16 {%0,%1,%2,%3}, [%4];"
      : "=r"(r[0]), "=r"(r[1]), "=r"(r[2]), "=r"(r[3])
      : "r"(addr));
}
__device__ __forceinline__ void ldsm_x4_t(uint32_t (&r)[4], uint32_t addr) {
  asm volatile(
      "ldmatrix.sync.aligned.m8n8.x4.trans.shared.b16 {%0,%1,%2,%3}, [%4];"
      : "=r"(r[0]), "=r"(r[1]), "=r"(r[2]), "=r"(r[3])
      : "r"(addr));
}

__device__ __forceinline__ void mma_16816(float (&c)[4], const uint32_t (&a)[4],
                                          const uint32_t b0, const uint32_t b1) {
  asm volatile(
      "mma.sync.aligned.m16n8k16.row.col.f32.bf16.bf16.f32 "
      "{%0,%1,%2,%3}, {%4,%5,%6,%7}, {%8,%9}, {%0,%1,%2,%3};"
      : "+f"(c[0]), "+f"(c[1]), "+f"(c[2]), "+f"(c[3])
      : "r"(a[0]), "r"(a[1]), "r"(a[2]), "r"(a[3]), "r"(b0), "r"(b1));
}

// ---------------------------------------------------------------------------
// Prep kernels
// ---------------------------------------------------------------------------
__global__ __launch_bounds__(256) void kprep_x(const float* __restrict__ x) {
  const int idx = blockIdx.x * 256 + threadIdx.x;  // 2M float4s
  const float4 v = ((const float4*)x)[idx];
  __nv_bfloat162 p0 = __floats2bfloat162_rn(v.x, v.y);
  __nv_bfloat162 p1 = __floats2bfloat162_rn(v.z, v.w);
  uint2 o;
  o.x = *(uint32_t*)&p0;
  o.y = *(uint32_t*)&p1;
  *(uint2*)&g_xb[(size_t)idx * 4] = o;
}

__global__ __launch_bounds__(256) void kprep_w1(const float* __restrict__ w1) {
  const int idx = blockIdx.x * 256 + threadIdx.x;  // 65536
  g_w1b[idx] = __float2bfloat16(w1[idx]);
}

__global__ __launch_bounds__(256) void kprep_wT(const float* __restrict__ wT) {
  const int idx = blockIdx.x * 256 + threadIdx.x;  // 131072
  const int g = idx >> 16, co2 = (idx >> 8) & 255, i = idx & 255;
  g_wTt[idx] = __float2bfloat16(wT[(size_t)(g * 256 + i) * 256 + co2]);
}

__global__ __launch_bounds__(256) void kprep_pat(const float* __restrict__ p) {
  const int idx = blockIdx.x * 256 + threadIdx.x;  // 524288
  const __nv_bfloat16 v = __float2bfloat16(p[idx]);
  const int m = idx >> 10;
  const int l = idx & 1023;
  g_pat[idx] = v;
  g_patT[(size_t)l * kM + m] = v;
}

// ---------------------------------------------------------------------------
// k1: HMMA grouped 1x1 conv + bias + ReLU + maxpool2 -> g_hp bf16
// per (b,g): C[o 256][l 2048] = W[o][i128] * X[i][l]; grid (16 l, 2 o, 32 bg)
// A tile [128 o][32 k] pad80B; B tile [32 k][128 l] pad272B (trans ldmatrix)
// ---------------------------------------------------------------------------
__global__ __launch_bounds__(256) void k1_hmma(const float* __restrict__ b1) {
  __shared__ __align__(16) char smem[37888];
  const int t = threadIdx.x, w = t >> 5, lid = t & 31;
  const int wm = w >> 2, wn = w & 3;
  const int bx = blockIdx.x, by = blockIdx.y, bz = blockIdx.z;
  const int b = bz >> 1, g = bz & 1;
  const uint32_t sAb = (uint32_t)__cvta_generic_to_shared(smem);
  const uint32_t sBb = sAb + 20480;
  const char* Ag = (const char*)(g_w1b + (size_t)(g * 256 + by * 128) * 128);
  const char* Bg =
      (const char*)(g_xb + ((size_t)(b * 256 + g * 128)) * 2048 + bx * 128);

  auto load_tile = [&](int s, int it) {
#pragma unroll
    for (int i = 0; i < 2; ++i) {
      const int idx = t + i * 256;
      const int row = idx >> 2, ch = idx & 3;
      cp_async16(sAb + s * 10240 + row * 80 + ch * 16,
                 Ag + row * 256 + it * 64 + ch * 16);
    }
#pragma unroll
    for (int i = 0; i < 2; ++i) {
      const int idx = t + i * 256;
      const int row = idx >> 4, ch = idx & 15;
      cp_async16(sBb + s * 8704 + row * 272 + ch * 16,
                 Bg + (size_t)(it * 32 + row) * 4096 + ch * 16);
    }
    CP_COMMIT();
  };

  float acc[4][4][4];
#pragma unroll
  for (int mt = 0; mt < 4; ++mt)
#pragma unroll
    for (int nt = 0; nt < 4; ++nt)
#pragma unroll
      for (int i = 0; i < 4; ++i) acc[mt][nt][i] = 0.f;

  load_tile(0, 0);
  const uint32_t aAddr0 = sAb + (wm * 64 + (lid & 15)) * 80 + (lid >> 4) * 16;
  const uint32_t bAddr0 =
      sBb + (((lid >> 3) & 1) * 8 + (lid & 7)) * 272 + (wn * 32 + (lid >> 4) * 8) * 2;

#pragma unroll 1
  for (int it = 0; it < 4; ++it) {
    if (it + 1 < 4) {
      load_tile((it + 1) & 1, it + 1);
      CP_WAIT(1);
    } else {
      CP_WAIT(0);
    }
    __syncthreads();
    const uint32_t sOA = (uint32_t)(it & 1) * 10240;
    const uint32_t sOB = (uint32_t)(it & 1) * 8704;
#pragma unroll
    for (int ks = 0; ks < 2; ++ks) {
      uint32_t afr[4][4];
      uint32_t bfr[4][2];
#pragma unroll
      for (int mt = 0; mt < 4; ++mt)
        ldsm_x4(afr[mt], aAddr0 + sOA + mt * 16 * 80 + ks * 32);
#pragma unroll
      for (int nt2 = 0; nt2 < 2; ++nt2) {
        uint32_t r4[4];
        ldsm_x4_t(r4, bAddr0 + sOB + ks * 16 * 272 + nt2 * 32);
        bfr[nt2 * 2 + 0][0] = r4[0]; bfr[nt2 * 2 + 0][1] = r4[1];
        bfr[nt2 * 2 + 1][0] = r4[2]; bfr[nt2 * 2 + 1][1] = r4[3];
      }
#pragma unroll
      for (int mt = 0; mt < 4; ++mt)
#pragma unroll
        for (int nt = 0; nt < 4; ++nt)
          mma_16816(acc[mt][nt], afr[mt], bfr[nt][0], bfr[nt][1]);
    }
    __syncthreads();
  }

  // epilogue: bias + relu + maxpool2 -> stage -> coalesced bf16 store
  __nv_bfloat16* sH = (__nv_bfloat16*)smem;  // [128][72]
#pragma unroll
  for (int mt = 0; mt < 4; ++mt) {
    const int m = wm * 64 + mt * 16 + (lid >> 2);
    const int og = g * 256 + by * 128 + m;
    const float bias0 = b1[og];
    const float bias1 = b1[og + 8];
#pragma unroll
    for (int nt = 0; nt < 4; ++nt) {
      const int np = wn * 16 + nt * 4 + (lid & 3);
      sH[m * 72 + np] =
          __float2bfloat16(fmaxf(fmaxf(acc[mt][nt][0], acc[mt][nt][1]) + bias0, 0.f));
      sH[(m + 8) * 72 + np] =
          __float2bfloat16(fmaxf(fmaxf(acc[mt][nt][2], acc[mt][nt][3]) + bias1, 0.f));
    }
  }
  __syncthreads();
  const size_t rowbase = (size_t)(b * 512 + g * 256 + by * 128);
  const int colbase = bx * 64;
#pragma unroll
  for (int p = 0; p < 4; ++p) {
    const int idx = t + p * 256;
    const int row = idx >> 3, ch = idx & 7;
    *(uint4*)&g_hp[(rowbase + row) * 1024 + colbase + ch * 8] =
        *(uint4*)&sH[row * 72 + ch * 8];
  }
}

// ---------------------------------------------------------------------------
// k2: HMMA GEMM scores = Hp @ P^T (K=1024) -> g_sc fp32
// ---------------------------------------------------------------------------
__global__ __launch_bounds__(256) void kgemm_scores() {
  constexpr int K = 1024, LDC = 512, ITERS = K / 32, ROWB = 80;
  __shared__ __align__(16) __nv_bfloat16 sA[2][128][40];
  __shared__ __align__(16) __nv_bfloat16 sB[2][128][40];

  const int t = threadIdx.x, w = t >> 5, lid = t & 31;
  const int wm = w >> 2, wn = w & 3;
  const int n0 = blockIdx.x * 128;
  const int r0 = blockIdx.y * 128;
  const uint32_t sAb = (uint32_t)__cvta_generic_to_shared(&sA[0][0][0]);
  const uint32_t sBb = (uint32_t)__cvta_generic_to_shared(&sB[0][0][0]);
  constexpr uint32_t STAGE = 128 * ROWB;
  const char* Ab = (const char*)(g_hp + (size_t)r0 * K);
  const char* Bb = (const char*)(g_pat + (size_t)n0 * K);
  const size_t pitch = (size_t)K * 2;
  const int ldrow[2] = {(t + 0) >> 2, (t + 256) >> 2};
  const int ldch[2] = {(t + 0) & 3, (t + 256) & 3};

  auto load_tile = [&](int s, int it) {
    const size_t kbyte = (size_t)it * 64;
#pragma unroll
    for (int i = 0; i < 2; ++i) {
      const size_t go = (size_t)ldrow[i] * pitch + kbyte + ldch[i] * 16;
      const uint32_t so = (uint32_t)s * STAGE + ldrow[i] * ROWB + ldch[i] * 16;
      cp_async16(sAb + so, Ab + go);
      cp_async16(sBb + so, Bb + go);
    }
    CP_COMMIT();
  };

  float acc[4][4][4];
#pragma unroll
  for (int mt = 0; mt < 4; ++mt)
#pragma unroll
    for (int nt = 0; nt < 4; ++nt)
#pragma unroll
      for (int i = 0; i < 4; ++i) acc[mt][nt][i] = 0.f;

  load_tile(0, 0);
  const uint32_t aAddr0 = sAb + (wm * 64 + (lid & 15)) * ROWB + (lid >> 4) * 16;
  const uint32_t bAddr0 =
      sBb + (wn * 32 + ((lid >> 4) ? 8 : 0) + (lid & 7)) * ROWB + ((lid >> 3) & 1) * 16;

#pragma unroll 1
  for (int it = 0; it < ITERS; ++it) {
    if (it + 1 < ITERS) {
      load_tile((it + 1) & 1, it + 1);
      CP_WAIT(1);
    } else {
      CP_WAIT(0);
    }
    __syncthreads();
    const uint32_t sOff = (uint32_t)(it & 1) * STAGE;
#pragma unroll
    for (int ks = 0; ks < 2; ++ks) {
      uint32_t afr[4][4];
      uint32_t bfr[4][2];
#pragma unroll
      for (int mt = 0; mt < 4; ++mt)
        ldsm_x4(afr[mt], aAddr0 + sOff + mt * 16 * ROWB + ks * 32);
#pragma unroll
      for (int nt2 = 0; nt2 < 2; ++nt2) {
        uint32_t r4[4];
        ldsm_x4(r4, bAddr0 + sOff + nt2 * 16 * ROWB + ks * 32);
        bfr[nt2 * 2 + 0][0] = r4[0]; bfr[nt2 * 2 + 0][1] = r4[1];
        bfr[nt2 * 2 + 1][0] = r4[2]; bfr[nt2 * 2 + 1][1] = r4[3];
      }
#pragma unroll
      for (int mt = 0; mt < 4; ++mt)
#pragma unroll
        for (int nt = 0; nt < 4; ++nt)
          mma_16816(acc[mt][nt], afr[mt], bfr[nt][0], bfr[nt][1]);
    }
    __syncthreads();
  }

  float* Crow = g_sc + (size_t)(r0 + wm * 64) * LDC + n0 + wn * 32;
  const int rr = lid >> 2;
  const int cc = (lid & 3) * 2;
#pragma unroll
  for (int mt = 0; mt < 4; ++mt)
#pragma unroll
    for (int nt = 0; nt < 4; ++nt) {
      float2 v0 = make_float2(acc[mt][nt][0], acc[mt][nt][1]);
      float2 v1 = make_float2(acc[mt][nt][2], acc[mt][nt][3]);
      *(float2*)&Crow[(size_t)(mt * 16 + rr) * LDC + nt * 8 + cc] = v0;
      *(float2*)&Crow[(size_t)(mt * 16 + rr + 8) * LDC + nt * 8 + cc] = v1;
    }
}

// ---------------------------------------------------------------------------
// k3: softmax over m=512, writes bf16 attn
// ---------------------------------------------------------------------------
__global__ __launch_bounds__(256) void k3_softmax() {
  const float* row = g_sc + (size_t)blockIdx.x * kM;
  __nv_bfloat16* orow = g_at + (size_t)blockIdx.x * kM;
  const int t = threadIdx.x;
  const float v0 = row[t];
  const float v1 = row[t + 256];
  float m = fmaxf(v0, v1);
  __shared__ float red[8];
  __shared__ float bval;
#pragma unroll
  for (int o = 16; o; o >>= 1) m = fmaxf(m, __shfl_xor_sync(0xffffffffu, m, o));
  if ((t & 31) == 0) red[t >> 5] = m;
  __syncthreads();
  if (t == 0) {
    float mm = red[0];
#pragma unroll
    for (int i = 1; i < 8; ++i) mm = fmaxf(mm, red[i]);
    bval = mm;
  }
  __syncthreads();
  m = bval;
  const float e0 = __expf(v0 - m), e1 = __expf(v1 - m);
  float s = e0 + e1;
#pragma unroll
  for (int o = 16; o; o >>= 1) s += __shfl_xor_sync(0xffffffffu, s, o);
  __syncthreads();
  if ((t & 31) == 0) red[t >> 5] = s;
  __syncthreads();
  if (t == 0) {
    float ss = red[0];
#pragma unroll
    for (int i = 1; i < 8; ++i) ss += red[i];
    bval = 1.f / ss;
  }
  __syncthreads();
  const float inv = bval;
  orow[t] = __float2bfloat16(e0 * inv);
  orow[t + 256] = __float2bfloat16(e1 * inv);
}

// ---------------------------------------------------------------------------
// k4: HMMA retrieval = Attn @ P (K=512), epilogue -> g_hrT bf16 transposed
// ---------------------------------------------------------------------------
__global__ __launch_bounds__(256) void kgemm_retrieve() {
  constexpr int K = 512, ITERS = K / 32, ROWB = 80;
  __shared__ __align__(16) char smem[40960];
  const int t = threadIdx.x, w = t >> 5, lid = t & 31;
  const int wm = w >> 2, wn = w & 3;
  const int n0 = blockIdx.x * 128;   // lp
  const int r0 = blockIdx.y * 128;   // attn row
  const uint32_t sAb = (uint32_t)__cvta_generic_to_shared(smem);
  const uint32_t sBb = sAb + 20480;
  constexpr uint32_t STAGE = 128 * ROWB;
  const char* Ab = (const char*)(g_at + (size_t)r0 * K);
  const char* Bb = (const char*)(g_patT + (size_t)n0 * K);
  const size_t pitch = (size_t)K * 2;
  const int ldrow[2] = {(t + 0) >> 2, (t + 256) >> 2};
  const int ldch[2] = {(t + 0) & 3, (t + 256) & 3};

  auto load_tile = [&](int s, int it) {
    const size_t kbyte = (size_t)it * 64;
#pragma unroll
    for (int i = 0; i < 2; ++i) {
      const size_t go = (size_t)ldrow[i] * pitch + kbyte + ldch[i] * 16;
      const uint32_t so = (uint32_t)s * STAGE + ldrow[i] * ROWB + ldch[i] * 16;
      cp_async16(sAb + so, Ab + go);
      cp_async16(sBb + so, Bb + go);
    }
    CP_COMMIT();
  };

  float acc[4][4][4];
#pragma unroll
  for (int mt = 0; mt < 4; ++mt)
#pragma unroll
    for (int nt = 0; nt < 4; ++nt)
#pragma unroll
      for (int i = 0; i < 4; ++i) acc[mt][nt][i] = 0.f;

  load_tile(0, 0);
  const uint32_t aAddr0 = sAb + (wm * 64 + (lid & 15)) * ROWB + (lid >> 4) * 16;
  const uint32_t bAddr0 =
      sBb + (wn * 32 + ((lid >> 4) ? 8 : 0) + (lid & 7)) * ROWB + ((lid >> 3) & 1) * 16;

#pragma unroll 1
  for (int it = 0; it < ITERS; ++it) {
    if (it + 1 < ITERS) {
      load_tile((it + 1) & 1, it + 1);
      CP_WAIT(1);
    } else {
      CP_WAIT(0);
    }
    __syncthreads();
    const uint32_t sOff = (uint32_t)(it & 1) * STAGE;
#pragma unroll
    for (int ks = 0; ks < 2; ++ks) {
      uint32_t afr[4][4];
      uint32_t bfr[4][2];
#pragma unroll
      for (int mt = 0; mt < 4; ++mt)
        ldsm_x4(afr[mt], aAddr0 + sOff + mt * 16 * ROWB + ks * 32);
#pragma unroll
      for (int nt2 = 0; nt2 < 2; ++nt2) {
        uint32_t r4[4];
        ldsm_x4(r4, bAddr0 + sOff + nt2 * 16 * ROWB + ks * 32);
        bfr[nt2 * 2 + 0][0] = r4[0]; bfr[nt2 * 2 + 0][1] = r4[1];
        bfr[nt2 * 2 + 1][0] = r4[2]; bfr[nt2 * 2 + 1][1] = r4[3];
      }
#pragma unroll
      for (int mt = 0; mt < 4; ++mt)
#pragma unroll
        for (int nt = 0; nt < 4; ++nt)
          mma_16816(acc[mt][nt], afr[mt], bfr[nt][0], bfr[nt][1]);
    }
    __syncthreads();
  }

  // transposed bf16 epilogue: stage [l][c], then coalesced rows of g_hrT
  __nv_bfloat16* sT = (__nv_bfloat16*)smem;  // [128 l][136 c]
#pragma unroll
  for (int mt = 0; mt < 4; ++mt) {
    const int m = wm * 64 + mt * 16 + (lid >> 2);
#pragma unroll
    for (int nt = 0; nt < 4; ++nt) {
      const int n = wn * 32 + nt * 8 + (lid & 3) * 2;
      sT[n * 136 + m] = __float2bfloat16(acc[mt][nt][0]);
      sT[(n + 1) * 136 + m] = __float2bfloat16(acc[mt][nt][1]);
      sT[n * 136 + m + 8] = __float2bfloat16(acc[mt][nt][2]);
      sT[(n + 1) * 136 + m + 8] = __float2bfloat16(acc[mt][nt][3]);
    }
  }
  __syncthreads();
  const int b = r0 >> 9;
  const int c0b = r0 & 511;
#pragma unroll
  for (int p = 0; p < 8; ++p) {
    const int idx = t + p * 256;
    const int row = idx >> 4, ch = idx & 15;
    *(uint4*)&g_hrT[((size_t)b * 1024 + n0 + row) * 512 + c0b + ch * 8] =
        *(uint4*)&sT[row * 136 + ch * 8];
  }
}

// ---------------------------------------------------------------------------
// k5: HMMA grouped ConvT(k=2,s=2) + bias + ReLU + residual
// per (b,g): C[lp 1024][co2 256] = hrT[lp][i] * wTt[co2][i], K=256
// grid (2 co2-tiles, 8 lp-tiles, 32 bg)
// ---------------------------------------------------------------------------
__global__ __launch_bounds__(256) void k5_hmma(
    const float* __restrict__ x, const float* __restrict__ bT,
    const float* __restrict__ rzp, float* __restrict__ out) {
  constexpr int ITERS = 8, ROWB = 80;
  __shared__ __align__(16) char smem[40960];
  const int t = threadIdx.x, w = t >> 5, lid = t & 31;
  const int wm = w >> 2, wn = w & 3;
  const int bx = blockIdx.x, by = blockIdx.y, bz = blockIdx.z;
  const int b = bz >> 1, g = bz & 1;
  const uint32_t sAb = (uint32_t)__cvta_generic_to_shared(smem);
  const uint32_t sBb = sAb + 20480;
  constexpr uint32_t STAGE = 128 * ROWB;
  const char* Ab =
      (const char*)(g_hrT + ((size_t)b * 1024 + by * 128) * 512 + g * 256);
  const char* Bb = (const char*)(g_wTt + (size_t)g * 65536 + (size_t)bx * 128 * 256);
  const int ldrowA[2] = {(t + 0) >> 2, (t + 256) >> 2};
  const int ldchA[2] = {(t + 0) & 3, (t + 256) & 3};

  auto load_tile = [&](int s, int it) {
#pragma unroll
    for (int i = 0; i < 2; ++i) {
      const int row = ldrowA[i], ch = ldchA[i];
      const uint32_t so = (uint32_t)s * STAGE + row * ROWB + ch * 16;
      cp_async16(sAb + so, Ab + (size_t)row * 1024 + it * 64 + ch * 16);
      cp_async16(sBb + so, Bb + (size_t)row * 512 + it * 64 + ch * 16);
    }
    CP_COMMIT();
  };

  float acc[4][4][4];
#pragma unroll
  for (int mt = 0; mt < 4; ++mt)
#pragma unroll
    for (int nt = 0; nt < 4; ++nt)
#pragma unroll
      for (int i = 0; i < 4; ++i) acc[mt][nt][i] = 0.f;

  load_tile(0, 0);
  const uint32_t aAddr0 = sAb + (wm * 64 + (lid & 15)) * ROWB + (lid >> 4) * 16;
  const uint32_t bAddr0 =
      sBb + (wn * 32 + ((lid >> 4) ? 8 : 0) + (lid & 7)) * ROWB + ((lid >> 3) & 1) * 16;

#pragma unroll 1
  for (int it = 0; it < ITERS; ++it) {
    if (it + 1 < ITERS) {
      load_tile((it + 1) & 1, it + 1);
      CP_WAIT(1);
    } else {
      CP_WAIT(0);
    }
    __syncthreads();
    const uint32_t sOff = (uint32_t)(it & 1) * STAGE;
#pragma unroll
    for (int ks = 0; ks < 2; ++ks) {
      uint32_t afr[4][4];
      uint32_t bfr[4][2];
#pragma unroll
      for (int mt = 0; mt < 4; ++mt)
        ldsm_x4(afr[mt], aAddr0 + sOff + mt * 16 * ROWB + ks * 32);
#pragma unroll
      for (int nt2 = 0; nt2 < 2; ++nt2) {
        uint32_t r4[4];
        ldsm_x4(r4, bAddr0 + sOff + nt2 * 16 * ROWB + ks * 32);
        bfr[nt2 * 2 + 0][0] = r4[0]; bfr[nt2 * 2 + 0][1] = r4[1];
        bfr[nt2 * 2 + 1][0] = r4[2]; bfr[nt2 * 2 + 1][1] = r4[3];
      }
#pragma unroll
      for (int mt = 0; mt < 4; ++mt)
#pragma unroll
        for (int nt = 0; nt < 4; ++nt)
          mma_16816(acc[mt][nt], afr[mt], bfr[nt][0], bfr[nt][1]);
    }
    __syncthreads();
  }

  // epilogue: bias + relu -> bf16 stage y[co 64][l 256]; then residual write
  __nv_bfloat16* sY = (__nv_bfloat16*)smem;  // [64][268]
  float biasv[4];
#pragma unroll
  for (int nt = 0; nt < 4; ++nt) {
    const int co_l = wn * 16 + nt * 4 + (lid & 3);
    biasv[nt] = bT[g * 128 + bx * 64 + co_l];
  }
#pragma unroll
  for (int mt = 0; mt < 4; ++mt) {
    const int m = wm * 64 + mt * 16 + (lid >> 2);
#pragma unroll
    for (int nt = 0; nt < 4; ++nt) {
      const int co_l = wn * 16 + nt * 4 + (lid & 3);
      __nv_bfloat162 p0 = __floats2bfloat162_rn(
          fmaxf(acc[mt][nt][0] + biasv[nt], 0.f),
          fmaxf(acc[mt][nt][1] + biasv[nt], 0.f));
      __nv_bfloat162 p1 = __floats2bfloat162_rn(
          fmaxf(acc[mt][nt][2] + biasv[nt], 0.f),
          fmaxf(acc[mt][nt][3] + biasv[nt], 0.f));
      *(__nv_bfloat162*)&sY[co_l * 268 + 2 * m] = p0;
      *(__nv_bfloat162*)&sY[co_l * 268 + 2 * (m + 8)] = p1;
    }
  }
  __syncthreads();
  const float rz = rzp[0];
  const int co_r = t >> 2;
  const int colb = (t & 3) * 4;
  const int cog = g * 128 + bx * 64 + co_r;
  const size_t rowoff = ((size_t)b * 256 + cog) * 2048 + by * 256;
#pragma unroll
  for (int j = 0; j < 16; ++j) {
    const int col = colb + j * 16;
    const uint32_t* yp = (const uint32_t*)&sY[co_r * 268 + col];
    __nv_bfloat162 y0 = *(const __nv_bfloat162*)&yp[0];
    __nv_bfloat162 y1 = *(const __nv_bfloat162*)&yp[1];
    const float4 xv = *(const float4*)(x + rowoff + col);
    float4 o4;
    o4.x = xv.x + rz * __bfloat162float(y0.x);
    o4.y = xv.y + rz * __bfloat162float(y0.y);
    o4.z = xv.z + rz * __bfloat162float(y1.x);
    o4.w = xv.w + rz * __bfloat162float(y1.y);
    *(float4*)(out + rowoff + col) = o4;
  }
}

// ---------------------------------------------------------------------------
extern "C" void kernel_launch(void* const* d_in, const int* in_sizes, int n_in,
                              void* d_out, int out_size) {
  (void)in_sizes; (void)n_in; (void)out_size;
  const float* x        = (const float*)d_in[0];
  const float* w1       = (const float*)d_in[1];
  const float* b1       = (const float*)d_in[2];
  const float* patterns = (const float*)d_in[3];
  const float* wT       = (const float*)d_in[4];
  const float* bT       = (const float*)d_in[5];
  const float* RZ       = (const float*)d_in[6];
  float* out            = (float*)d_out;

  kprep_x<<<8192, 256>>>(x);
  kprep_w1<<<256, 256>>>(w1);
  kprep_wT<<<512, 256>>>(wT);
  kprep_pat<<<2048, 256>>>(patterns);
  k1_hmma<<<dim3(16, 2, 32), 256>>>(b1);
  kgemm_scores<<<dim3(kM / 128, kRows / 128), 256>>>();
  k3_softmax<<<kRows, 256>>>();
  kgemm_retrieve<<<dim3(kLP / 128, kRows / 128), 256>>>();
  k5_hmma<<<dim3(2, 8, 32), 256>>>(x, bT, RZ, out);
}

// round 5
// speedup vs baseline: 5.2483x; 1.1143x over previous
#include <cuda_runtime.h>
#include <cuda_bf16.h>
#include <cstdint>

namespace {
constexpr int kB   = 16;
constexpr int kCIN = 256;
constexpr int kL   = 2048;
constexpr int kHID = 512;
constexpr int kM   = 512;
constexpr int kLP  = 1024;
constexpr int kRows = kB * kHID;  // 8192
}

// ---------------- scratch (device globals; no allocation) -------------------
__device__ __align__(16) __nv_bfloat16 g_w1b[kHID * 128];      // w1 bf16
__device__ __align__(16) __nv_bfloat16 g_wTt[2 * 256 * 256];   // wT^T bf16 [g][co2][i]
__device__ __align__(16) __nv_bfloat16 g_hp[kRows * kLP];      // pooled hidden bf16
__device__ __align__(16) __nv_bfloat16 g_scb[kRows * kM];      // scores bf16
__device__ __align__(16) __nv_bfloat16 g_at[kRows * kM];       // attn bf16
__device__ __align__(16) __nv_bfloat16 g_hrT[kB * kLP * kHID]; // retrieved^T bf16 [b][lp][c]
__device__ __align__(16) __nv_bfloat16 g_pat[kM * kLP];        // patterns bf16 [m][lp]

// ---------------- PTX helpers ------------------------------------------------
__device__ __forceinline__ void cp_async16(uint32_t dst, const void* src) {
  asm volatile("cp.async.cg.shared.global [%0], [%1], 16;\n" ::"r"(dst), "l"(src));
}
#define CP_COMMIT() asm volatile("cp.async.commit_group;\n" ::: "memory")
#define CP_WAIT(n) asm volatile("cp.async.wait_group %0;\n" ::"n"(n) : "memory")

__device__ __forceinline__ void ldsm_x4(uint32_t (&r)[4], uint32_t addr) {
  asm volatile(
      "ldmatrix.sync.aligned.m8n8.x4.shared.b16 {%0,%1,%2,%3}, [%4];"
      : "=r"(r[0]), "=r"(r[1]), "=r"(r[2]), "=r"(r[3])
      : "r"(addr));
}
__device__ __forceinline__ void ldsm_x4_t(uint32_t (&r)[4], uint32_t addr) {
  asm volatile(
      "ldmatrix.sync.aligned.m8n8.x4.trans.shared.b16 {%0,%1,%2,%3}, [%4];"
      : "=r"(r[0]), "=r"(r[1]), "=r"(r[2]), "=r"(r[3])
      : "r"(addr));
}

__device__ __forceinline__ void mma_16816(float (&c)[4], const uint32_t (&a)[4],
                                          const uint32_t b0, const uint32_t b1) {
  asm volatile(
      "mma.sync.aligned.m16n8k16.row.col.f32.bf16.bf16.f32 "
      "{%0,%1,%2,%3}, {%4,%5,%6,%7}, {%8,%9}, {%0,%1,%2,%3};"
      : "+f"(c[0]), "+f"(c[1]), "+f"(c[2]), "+f"(c[3])
      : "r"(a[0]), "r"(a[1]), "r"(a[2]), "r"(a[3]), "r"(b0), "r"(b1));
}

__device__ __forceinline__ uint32_t pack_bf16(float a, float b) {
  __nv_bfloat162 p = __floats2bfloat162_rn(a, b);
  return *(uint32_t*)&p;
}

// ---------------------------------------------------------------------------
// Single prep kernel: w1 -> g_w1b, wT -> g_wTt (transposed), pat -> g_pat
// ---------------------------------------------------------------------------
__global__ __launch_bounds__(256) void kprep_all(const float* __restrict__ w1,
                                                 const float* __restrict__ wT,
                                                 const float* __restrict__ pat) {
  const int bid = blockIdx.x;
  const int t = threadIdx.x;
  if (bid < 64) {  // w1: 65536 floats, vec4
    const int idx = (bid * 256 + t) * 4;
    const float4 v = *(const float4*)(w1 + idx);
    uint2 o;
    o.x = pack_bf16(v.x, v.y);
    o.y = pack_bf16(v.z, v.w);
    *(uint2*)&g_w1b[idx] = o;
  } else if (bid < 576) {  // wT transpose scatter: 131072 scalar
    const int idx = (bid - 64) * 256 + t;
    const int g = idx >> 16, co2 = (idx >> 8) & 255, i = idx & 255;
    g_wTt[idx] = __float2bfloat16(wT[(size_t)(g * 256 + i) * 256 + co2]);
  } else {  // patterns: 524288 floats, vec4
    const int idx = ((bid - 576) * 256 + t) * 4;
    const float4 v = *(const float4*)(pat + idx);
    uint2 o;
    o.x = pack_bf16(v.x, v.y);
    o.y = pack_bf16(v.z, v.w);
    *(uint2*)&g_pat[idx] = o;
  }
}

// ---------------------------------------------------------------------------
// k1: HMMA grouped 1x1 conv + bias + ReLU + maxpool2 -> g_hp bf16
// Reads fp32 x directly; per-thread LDG.128 prefetch -> cvt -> STS bf16 tile.
// A tile (w1 bf16) via cp.async. grid (16 l, 2 o, 32 bg)
// ---------------------------------------------------------------------------
__global__ __launch_bounds__(256) void k1_hmma(const float* __restrict__ x,
                                               const float* __restrict__ b1) {
  __shared__ __align__(16) char smem[37888];  // A 2x10240 | B 2x8704
  const int t = threadIdx.x, w = t >> 5, lid = t & 31;
  const int wm = w >> 2, wn = w & 3;
  const int bx = blockIdx.x, by = blockIdx.y, bz = blockIdx.z;
  const int b = bz >> 1, g = bz & 1;
  const uint32_t sAb = (uint32_t)__cvta_generic_to_shared(smem);
  const char* Ag = (const char*)(g_w1b + (size_t)(g * 256 + by * 128) * 128);
  const float* xB = x + ((size_t)(b * 256 + g * 128)) * 2048 + bx * 128;

  const int brow = t >> 3, bcq = t & 7;
  const float* xrow = xB + (size_t)brow * 2048 + bcq * 16;

  auto ldA = [&](int s, int it) {
#pragma unroll
    for (int i = 0; i < 2; ++i) {
      const int idx = t + i * 256;
      const int row = idx >> 2, ch = idx & 3;
      cp_async16(sAb + s * 10240 + row * 80 + ch * 16,
                 Ag + row * 256 + it * 64 + ch * 16);
    }
    CP_COMMIT();
  };

  float4 v[4];
  auto ldB = [&](int it) {
    const float4* p = (const float4*)(xrow + (size_t)it * 32 * 2048);
#pragma unroll
    for (int q = 0; q < 4; ++q) v[q] = p[q];
  };
  auto stB = [&](int s) {
    uint4 q0, q1;
    q0.x = pack_bf16(v[0].x, v[0].y); q0.y = pack_bf16(v[0].z, v[0].w);
    q0.z = pack_bf16(v[1].x, v[1].y); q0.w = pack_bf16(v[1].z, v[1].w);
    q1.x = pack_bf16(v[2].x, v[2].y); q1.y = pack_bf16(v[2].z, v[2].w);
    q1.z = pack_bf16(v[3].x, v[3].y); q1.w = pack_bf16(v[3].z, v[3].w);
    char* d = smem + 20480 + s * 8704 + brow * 272 + bcq * 32;
    *(uint4*)d = q0;
    *((uint4*)d + 1) = q1;
  };

  float acc[4][4][4];
#pragma unroll
  for (int mt = 0; mt < 4; ++mt)
#pragma unroll
    for (int nt = 0; nt < 4; ++nt)
#pragma unroll
      for (int i = 0; i < 4; ++i) acc[mt][nt][i] = 0.f;

  ldA(0, 0);
  ldB(0);
  const uint32_t aAddr0 = sAb + (wm * 64 + (lid & 15)) * 80 + (lid >> 4) * 16;
  const uint32_t bAddr0 = sAb + 20480 +
      (((lid >> 3) & 1) * 8 + (lid & 7)) * 272 + (wn * 32 + (lid >> 4) * 8) * 2;

#pragma unroll 1
  for (int it = 0; it < 4; ++it) {
    if (it + 1 < 4) {
      ldA((it + 1) & 1, it + 1);
      CP_WAIT(1);
    } else {
      CP_WAIT(0);
    }
    stB(it & 1);
    __syncthreads();
    if (it + 1 < 4) ldB(it + 1);
    const uint32_t sOA = (uint32_t)(it & 1) * 10240;
    const uint32_t sOB = (uint32_t)(it & 1) * 8704;
#pragma unroll
    for (int ks = 0; ks < 2; ++ks) {
      uint32_t afr[4][4];
      uint32_t bfr[4][2];
#pragma unroll
      for (int mt = 0; mt < 4; ++mt)
        ldsm_x4(afr[mt], aAddr0 + sOA + mt * 16 * 80 + ks * 32);
#pragma unroll
      for (int nt2 = 0; nt2 < 2; ++nt2) {
        uint32_t r4[4];
        ldsm_x4_t(r4, bAddr0 + sOB + ks * 16 * 272 + nt2 * 32);
        bfr[nt2 * 2 + 0][0] = r4[0]; bfr[nt2 * 2 + 0][1] = r4[1];
        bfr[nt2 * 2 + 1][0] = r4[2]; bfr[nt2 * 2 + 1][1] = r4[3];
      }
#pragma unroll
      for (int mt = 0; mt < 4; ++mt)
#pragma unroll
        for (int nt = 0; nt < 4; ++nt)
          mma_16816(acc[mt][nt], afr[mt], bfr[nt][0], bfr[nt][1]);
    }
    __syncthreads();
  }

  // epilogue: bias + relu + maxpool2 -> stage -> coalesced bf16 store
  __nv_bfloat16* sH = (__nv_bfloat16*)smem;  // [128][72]
#pragma unroll
  for (int mt = 0; mt < 4; ++mt) {
    const int m = wm * 64 + mt * 16 + (lid >> 2);
    const int og = g * 256 + by * 128 + m;
    const float bias0 = b1[og];
    const float bias1 = b1[og + 8];
#pragma unroll
    for (int nt = 0; nt < 4; ++nt) {
      const int np = wn * 16 + nt * 4 + (lid & 3);
      sH[m * 72 + np] =
          __float2bfloat16(fmaxf(fmaxf(acc[mt][nt][0], acc[mt][nt][1]) + bias0, 0.f));
      sH[(m + 8) * 72 + np] =
          __float2bfloat16(fmaxf(fmaxf(acc[mt][nt][2], acc[mt][nt][3]) + bias1, 0.f));
    }
  }
  __syncthreads();
  const size_t rowbase = (size_t)(b * 512 + g * 256 + by * 128);
  const int colbase = bx * 64;
#pragma unroll
  for (int p = 0; p < 4; ++p) {
    const int idx = t + p * 256;
    const int row = idx >> 3, ch = idx & 7;
    *(uint4*)&g_hp[(rowbase + row) * 1024 + colbase + ch * 8] =
        *(uint4*)&sH[row * 72 + ch * 8];
  }
}

// ---------------------------------------------------------------------------
// k2: HMMA GEMM scores = Hp @ P^T (K=1024) -> g_scb bf16
// ---------------------------------------------------------------------------
__global__ __launch_bounds__(256) void kgemm_scores() {
  constexpr int K = 1024, ITERS = K / 32, ROWB = 80;
  __shared__ __align__(16) __nv_bfloat16 sA[2][128][40];
  __shared__ __align__(16) __nv_bfloat16 sB[2][128][40];

  const int t = threadIdx.x, w = t >> 5, lid = t & 31;
  const int wm = w >> 2, wn = w & 3;
  const int n0 = blockIdx.x * 128;
  const int r0 = blockIdx.y * 128;
  const uint32_t sAb = (uint32_t)__cvta_generic_to_shared(&sA[0][0][0]);
  const uint32_t sBb = (uint32_t)__cvta_generic_to_shared(&sB[0][0][0]);
  constexpr uint32_t STAGE = 128 * ROWB;
  const char* Ab = (const char*)(g_hp + (size_t)r0 * K);
  const char* Bb = (const char*)(g_pat + (size_t)n0 * K);
  const size_t pitch = (size_t)K * 2;
  const int ldrow[2] = {(t + 0) >> 2, (t + 256) >> 2};
  const int ldch[2] = {(t + 0) & 3, (t + 256) & 3};

  auto load_tile = [&](int s, int it) {
    const size_t kbyte = (size_t)it * 64;
#pragma unroll
    for (int i = 0; i < 2; ++i) {
      const size_t go = (size_t)ldrow[i] * pitch + kbyte + ldch[i] * 16;
      const uint32_t so = (uint32_t)s * STAGE + ldrow[i] * ROWB + ldch[i] * 16;
      cp_async16(sAb + so, Ab + go);
      cp_async16(sBb + so, Bb + go);
    }
    CP_COMMIT();
  };

  float acc[4][4][4];
#pragma unroll
  for (int mt = 0; mt < 4; ++mt)
#pragma unroll
    for (int nt = 0; nt < 4; ++nt)
#pragma unroll
      for (int i = 0; i < 4; ++i) acc[mt][nt][i] = 0.f;

  load_tile(0, 0);
  const uint32_t aAddr0 = sAb + (wm * 64 + (lid & 15)) * ROWB + (lid >> 4) * 16;
  const uint32_t bAddr0 =
      sBb + (wn * 32 + ((lid >> 4) ? 8 : 0) + (lid & 7)) * ROWB + ((lid >> 3) & 1) * 16;

#pragma unroll 1
  for (int it = 0; it < ITERS; ++it) {
    if (it + 1 < ITERS) {
      load_tile((it + 1) & 1, it + 1);
      CP_WAIT(1);
    } else {
      CP_WAIT(0);
    }
    __syncthreads();
    const uint32_t sOff = (uint32_t)(it & 1) * STAGE;
#pragma unroll
    for (int ks = 0; ks < 2; ++ks) {
      uint32_t afr[4][4];
      uint32_t bfr[4][2];
#pragma unroll
      for (int mt = 0; mt < 4; ++mt)
        ldsm_x4(afr[mt], aAddr0 + sOff + mt * 16 * ROWB + ks * 32);
#pragma unroll
      for (int nt2 = 0; nt2 < 2; ++nt2) {
        uint32_t r4[4];
        ldsm_x4(r4, bAddr0 + sOff + nt2 * 16 * ROWB + ks * 32);
        bfr[nt2 * 2 + 0][0] = r4[0]; bfr[nt2 * 2 + 0][1] = r4[1];
        bfr[nt2 * 2 + 1][0] = r4[2]; bfr[nt2 * 2 + 1][1] = r4[3];
      }
#pragma unroll
      for (int mt = 0; mt < 4; ++mt)
#pragma unroll
        for (int nt = 0; nt < 4; ++nt)
          mma_16816(acc[mt][nt], afr[mt], bfr[nt][0], bfr[nt][1]);
    }
    __syncthreads();
  }

  __nv_bfloat16* Crow = g_scb + (size_t)(r0 + wm * 64) * 512 + n0 + wn * 32;
  const int rr = lid >> 2;
  const int cc = (lid & 3) * 2;
#pragma unroll
  for (int mt = 0; mt < 4; ++mt)
#pragma unroll
    for (int nt = 0; nt < 4; ++nt) {
      *(uint32_t*)&Crow[(size_t)(mt * 16 + rr) * 512 + nt * 8 + cc] =
          pack_bf16(acc[mt][nt][0], acc[mt][nt][1]);
      *(uint32_t*)&Crow[(size_t)(mt * 16 + rr + 8) * 512 + nt * 8 + cc] =
          pack_bf16(acc[mt][nt][2], acc[mt][nt][3]);
    }
}

// ---------------------------------------------------------------------------
// k3: softmax over m=512 — warp per row, bf16 in/out, no block barriers
// ---------------------------------------------------------------------------
__global__ __launch_bounds__(256) void k3_softmax() {
  const int wid = threadIdx.x >> 5, lane = threadIdx.x & 31;
  const size_t row = (size_t)blockIdx.x * 8 + wid;
  const uint4* rp = (const uint4*)(g_scb + row * 512);
  const uint4 q0 = rp[lane];
  const uint4 q1 = rp[lane + 32];

  float f[16];
  {
    const uint32_t us[8] = {q0.x, q0.y, q0.z, q0.w, q1.x, q1.y, q1.z, q1.w};
#pragma unroll
    for (int i = 0; i < 8; ++i) {
      const __nv_bfloat162 p = *(const __nv_bfloat162*)&us[i];
      f[2 * i] = __bfloat162float(p.x);
      f[2 * i + 1] = __bfloat162float(p.y);
    }
  }
  float m = f[0];
#pragma unroll
  for (int i = 1; i < 16; ++i) m = fmaxf(m, f[i]);
#pragma unroll
  for (int o = 16; o; o >>= 1) m = fmaxf(m, __shfl_xor_sync(0xffffffffu, m, o));
  float s = 0.f;
#pragma unroll
  for (int i = 0; i < 16; ++i) {
    f[i] = __expf(f[i] - m);
    s += f[i];
  }
#pragma unroll
  for (int o = 16; o; o >>= 1) s += __shfl_xor_sync(0xffffffffu, s, o);
  const float inv = 1.f / s;

  uint4 o0, o1;
  o0.x = pack_bf16(f[0] * inv, f[1] * inv);
  o0.y = pack_bf16(f[2] * inv, f[3] * inv);
  o0.z = pack_bf16(f[4] * inv, f[5] * inv);
  o0.w = pack_bf16(f[6] * inv, f[7] * inv);
  o1.x = pack_bf16(f[8] * inv, f[9] * inv);
  o1.y = pack_bf16(f[10] * inv, f[11] * inv);
  o1.z = pack_bf16(f[12] * inv, f[13] * inv);
  o1.w = pack_bf16(f[14] * inv, f[15] * inv);
  uint4* op = (uint4*)(g_at + row * 512);
  op[lane] = o0;
  op[lane + 32] = o1;
}

// ---------------------------------------------------------------------------
// k4: HMMA retrieval = Attn @ P (K=512) with trans-ldmatrix B from g_pat;
// epilogue -> g_hrT bf16 transposed
// ---------------------------------------------------------------------------
__global__ __launch_bounds__(256) void kgemm_retrieve() {
  constexpr int ITERS = 16;
  __shared__ __align__(16) char smem[37888];  // A 2x10240 | B 2x8704
  const int t = threadIdx.x, w = t >> 5, lid = t & 31;
  const int wm = w >> 2, wn = w & 3;
  const int n0 = blockIdx.x * 128;  // lp
  const int r0 = blockIdx.y * 128;  // attn row
  const uint32_t sAb = (uint32_t)__cvta_generic_to_shared(smem);
  const uint32_t sBb = sAb + 20480;
  const char* Ab = (const char*)(g_at + (size_t)r0 * 512);
  const char* Bb = (const char*)(g_pat + n0);

  auto load_tile = [&](int s, int it) {
#pragma unroll
    for (int i = 0; i < 2; ++i) {  // A: 128 rows x 64B
      const int idx = t + i * 256;
      const int row = idx >> 2, ch = idx & 3;
      cp_async16(sAb + s * 10240 + row * 80 + ch * 16,
                 Ab + (size_t)row * 1024 + it * 64 + ch * 16);
    }
#pragma unroll
    for (int i = 0; i < 2; ++i) {  // B: 32 m-rows x 256B from g_pat
      const int idx = t + i * 256;
      const int row = idx >> 4, ch = idx & 15;
      cp_async16(sBb + s * 8704 + row * 272 + ch * 16,
                 Bb + (size_t)(it * 32 + row) * 2048 + ch * 16);
    }
    CP_COMMIT();
  };

  float acc[4][4][4];
#pragma unroll
  for (int mt = 0; mt < 4; ++mt)
#pragma unroll
    for (int nt = 0; nt < 4; ++nt)
#pragma unroll
      for (int i = 0; i < 4; ++i) acc[mt][nt][i] = 0.f;

  load_tile(0, 0);
  const uint32_t aAddr0 = sAb + (wm * 64 + (lid & 15)) * 80 + (lid >> 4) * 16;
  const uint32_t bAddr0 =
      sBb + (((lid >> 3) & 1) * 8 + (lid & 7)) * 272 + (wn * 32 + (lid >> 4) * 8) * 2;

#pragma unroll 1
  for (int it = 0; it < ITERS; ++it) {
    if (it + 1 < ITERS) {
      load_tile((it + 1) & 1, it + 1);
      CP_WAIT(1);
    } else {
      CP_WAIT(0);
    }
    __syncthreads();
    const uint32_t sOA = (uint32_t)(it & 1) * 10240;
    const uint32_t sOB = (uint32_t)(it & 1) * 8704;
#pragma unroll
    for (int ks = 0; ks < 2; ++ks) {
      uint32_t afr[4][4];
      uint32_t bfr[4][2];
#pragma unroll
      for (int mt = 0; mt < 4; ++mt)
        ldsm_x4(afr[mt], aAddr0 + sOA + mt * 16 * 80 + ks * 32);
#pragma unroll
      for (int nt2 = 0; nt2 < 2; ++nt2) {
        uint32_t r4[4];
        ldsm_x4_t(r4, bAddr0 + sOB + ks * 16 * 272 + nt2 * 32);
        bfr[nt2 * 2 + 0][0] = r4[0]; bfr[nt2 * 2 + 0][1] = r4[1];
        bfr[nt2 * 2 + 1][0] = r4[2]; bfr[nt2 * 2 + 1][1] = r4[3];
      }
#pragma unroll
      for (int mt = 0; mt < 4; ++mt)
#pragma unroll
        for (int nt = 0; nt < 4; ++nt)
          mma_16816(acc[mt][nt], afr[mt], bfr[nt][0], bfr[nt][1]);
    }
    __syncthreads();
  }

  // transposed bf16 epilogue: stage [l][c], then coalesced rows of g_hrT
  __nv_bfloat16* sT = (__nv_bfloat16*)smem;  // [128 l][136 c]
#pragma unroll
  for (int mt = 0; mt < 4; ++mt) {
    const int m = wm * 64 + mt * 16 + (lid >> 2);
#pragma unroll
    for (int nt = 0; nt < 4; ++nt) {
      const int n = wn * 32 + nt * 8 + (lid & 3) * 2;
      sT[n * 136 + m] = __float2bfloat16(acc[mt][nt][0]);
      sT[(n + 1) * 136 + m] = __float2bfloat16(acc[mt][nt][1]);
      sT[n * 136 + m + 8] = __float2bfloat16(acc[mt][nt][2]);
      sT[(n + 1) * 136 + m + 8] = __float2bfloat16(acc[mt][nt][3]);
    }
  }
  __syncthreads();
  const int b = r0 >> 9;
  const int c0b = r0 & 511;
#pragma unroll
  for (int p = 0; p < 8; ++p) {
    const int idx = t + p * 256;
    const int row = idx >> 4, ch = idx & 15;
    *(uint4*)&g_hrT[((size_t)b * 1024 + n0 + row) * 512 + c0b + ch * 8] =
        *(uint4*)&sT[row * 136 + ch * 8];
  }
}

// ---------------------------------------------------------------------------
// k5: HMMA grouped ConvT(k=2,s=2) + bias + ReLU + residual
// ---------------------------------------------------------------------------
__global__ __launch_bounds__(256) void k5_hmma(
    const float* __restrict__ x, const float* __restrict__ bT,
    const float* __restrict__ rzp, float* __restrict__ out) {
  constexpr int ITERS = 8, ROWB = 80;
  __shared__ __align__(16) char smem[40960];
  const int t = threadIdx.x, w = t >> 5, lid = t & 31;
  const int wm = w >> 2, wn = w & 3;
  const int bx = blockIdx.x, by = blockIdx.y, bz = blockIdx.z;
  const int b = bz >> 1, g = bz & 1;
  const uint32_t sAb = (uint32_t)__cvta_generic_to_shared(smem);
  const uint32_t sBb = sAb + 20480;
  constexpr uint32_t STAGE = 128 * ROWB;
  const char* Ab =
      (const char*)(g_hrT + ((size_t)b * 1024 + by * 128) * 512 + g * 256);
  const char* Bb = (const char*)(g_wTt + (size_t)g * 65536 + (size_t)bx * 128 * 256);
  const int ldrowA[2] = {(t + 0) >> 2, (t + 256) >> 2};
  const int ldchA[2] = {(t + 0) & 3, (t + 256) & 3};

  auto load_tile = [&](int s, int it) {
#pragma unroll
    for (int i = 0; i < 2; ++i) {
      const int row = ldrowA[i], ch = ldchA[i];
      const uint32_t so = (uint32_t)s * STAGE + row * ROWB + ch * 16;
      cp_async16(sAb + so, Ab + (size_t)row * 1024 + it * 64 + ch * 16);
      cp_async16(sBb + so, Bb + (size_t)row * 512 + it * 64 + ch * 16);
    }
    CP_COMMIT();
  };

  float acc[4][4][4];
#pragma unroll
  for (int mt = 0; mt < 4; ++mt)
#pragma unroll
    for (int nt = 0; nt < 4; ++nt)
#pragma unroll
      for (int i = 0; i < 4; ++i) acc[mt][nt][i] = 0.f;

  load_tile(0, 0);
  const uint32_t aAddr0 = sAb + (wm * 64 + (lid & 15)) * ROWB + (lid >> 4) * 16;
  const uint32_t bAddr0 =
      sBb + (wn * 32 + ((lid >> 4) ? 8 : 0) + (lid & 7)) * ROWB + ((lid >> 3) & 1) * 16;

#pragma unroll 1
  for (int it = 0; it < ITERS; ++it) {
    if (it + 1 < ITERS) {
      load_tile((it + 1) & 1, it + 1);
      CP_WAIT(1);
    } else {
      CP_WAIT(0);
    }
    __syncthreads();
    const uint32_t sOff = (uint32_t)(it & 1) * STAGE;
#pragma unroll
    for (int ks = 0; ks < 2; ++ks) {
      uint32_t afr[4][4];
      uint32_t bfr[4][2];
#pragma unroll
      for (int mt = 0; mt < 4; ++mt)
        ldsm_x4(afr[mt], aAddr0 + sOff + mt * 16 * ROWB + ks * 32);
#pragma unroll
      for (int nt2 = 0; nt2 < 2; ++nt2) {
        uint32_t r4[4];
        ldsm_x4(r4, bAddr0 + sOff + nt2 * 16 * ROWB + ks * 32);
        bfr[nt2 * 2 + 0][0] = r4[0]; bfr[nt2 * 2 + 0][1] = r4[1];
        bfr[nt2 * 2 + 1][0] = r4[2]; bfr[nt2 * 2 + 1][1] = r4[3];
      }
#pragma unroll
      for (int mt = 0; mt < 4; ++mt)
#pragma unroll
        for (int nt = 0; nt < 4; ++nt)
          mma_16816(acc[mt][nt], afr[mt], bfr[nt][0], bfr[nt][1]);
    }
    __syncthreads();
  }

  // epilogue: bias + relu -> bf16 stage y[co 64][l 256]; then residual write
  __nv_bfloat16* sY = (__nv_bfloat16*)smem;  // [64][268]
  float biasv[4];
#pragma unroll
  for (int nt = 0; nt < 4; ++nt) {
    const int co_l = wn * 16 + nt * 4 + (lid & 3);
    biasv[nt] = bT[g * 128 + bx * 64 + co_l];
  }
#pragma unroll
  for (int mt = 0; mt < 4; ++mt) {
    const int m = wm * 64 + mt * 16 + (lid >> 2);
#pragma unroll
    for (int nt = 0; nt < 4; ++nt) {
      const int co_l = wn * 16 + nt * 4 + (lid & 3);
      __nv_bfloat162 p0 = __floats2bfloat162_rn(
          fmaxf(acc[mt][nt][0] + biasv[nt], 0.f),
          fmaxf(acc[mt][nt][1] + biasv[nt], 0.f));
      __nv_bfloat162 p1 = __floats2bfloat162_rn(
          fmaxf(acc[mt][nt][2] + biasv[nt], 0.f),
          fmaxf(acc[mt][nt][3] + biasv[nt], 0.f));
      *(__nv_bfloat162*)&sY[co_l * 268 + 2 * m] = p0;
      *(__nv_bfloat162*)&sY[co_l * 268 + 2 * (m + 8)] = p1;
    }
  }
  __syncthreads();
  const float rz = rzp[0];
  const int co_r = t >> 2;
  const int colb = (t & 3) * 4;
  const int cog = g * 128 + bx * 64 + co_r;
  const size_t rowoff = ((size_t)b * 256 + cog) * 2048 + by * 256;
#pragma unroll
  for (int j = 0; j < 16; ++j) {
    const int col = colb + j * 16;
    const uint32_t* yp = (const uint32_t*)&sY[co_r * 268 + col];
    __nv_bfloat162 y0 = *(const __nv_bfloat162*)&yp[0];
    __nv_bfloat162 y1 = *(const __nv_bfloat162*)&yp[1];
    const float4 xv = *(const float4*)(x + rowoff + col);
    float4 o4;
    o4.x = xv.x + rz * __bfloat162float(y0.x);
    o4.y = xv.y + rz * __bfloat162float(y0.y);
    o4.z = xv.z + rz * __bfloat162float(y1.x);
    o4.w = xv.w + rz * __bfloat162float(y1.y);
    *(float4*)(out + rowoff + col) = o4;
  }
}

// ---------------------------------------------------------------------------
extern "C" void kernel_launch(void* const* d_in, const int* in_sizes, int n_in,
                              void* d_out, int out_size) {
  (void)in_sizes; (void)n_in; (void)out_size;
  const float* x        = (const float*)d_in[0];
  const float* w1       = (const float*)d_in[1];
  const float* b1       = (const float*)d_in[2];
  const float* patterns = (const float*)d_in[3];
  const float* wT       = (const float*)d_in[4];
  const float* bT       = (const float*)d_in[5];
  const float* RZ       = (const float*)d_in[6];
  float* out            = (float*)d_out;

  kprep_all<<<1088, 256>>>(w1, wT, patterns);
  k1_hmma<<<dim3(16, 2, 32), 256>>>(x, b1);
  kgemm_scores<<<dim3(kM / 128, kRows / 128), 256>>>();
  k3_softmax<<<kRows / 8, 256>>>();
  kgemm_retrieve<<<dim3(kLP / 128, kRows / 128), 256>>>();
  k5_hmma<<<dim3(2, 8, 32), 256>>>(x, bT, RZ, out);
}